// round 2
// baseline (speedup 1.0000x reference)
#include <cuda_runtime.h>

#define N_NODES  100000
#define N_EDGES  1600000
#define D        128
#define N_LAYERS 7
#define N_GRAPHS 64
#define N_CLASSES 10
#define SNN_IN   512
#define SNN_HID  1024
#define SNN_BETA 0.85f

// ---------------- scratch (no allocations allowed) ----------------
__device__ float g_h0[N_NODES * D];
__device__ float g_h1[N_NODES * D];
__device__ float g_agg[N_NODES * D];
__device__ int   g_counts[N_NODES];
__device__ int   g_rowptr[N_NODES + 1];
__device__ int   g_wptr[N_NODES];
__device__ int   g_esrc[N_EDGES];
__device__ int   g_blocksums[256];
__device__ float g_pool[N_GRAPHS * D];
__device__ float g_cnt[N_GRAPHS];
__device__ float g_snnh[N_GRAPHS * SNN_HID];
__device__ int   g_flags[2];   // [0]: edge_index is int64, [1]: batch is int64

// ---------------- helpers ----------------
__device__ __forceinline__ int ld_idx(const void* p, long long i, int is64) {
    if (is64) return (int)((const long long*)p)[i];
    return ((const int*)p)[i];
}

// Detect whether index buffers are int64 (little-endian: high 32-bit words all 0)
// or int32. For batch (sorted, early values are 0) we probe the tail where
// graph ids are ~63 (nonzero) in the int32 case.
__global__ void k_detect(const unsigned int* ei, const unsigned int* bt) {
    if (blockIdx.x == 0 && threadIdx.x == 0) {
        int e64 = 1;
        for (int i = 0; i < 1000; i++) {
            if (ei[2 * i + 1] != 0u) { e64 = 0; break; }
        }
        int b64 = 1;
        for (int i = 0; i < 500; i++) {
            if (bt[99999 - 2 * i] != 0u) { b64 = 0; break; }
        }
        g_flags[0] = e64;
        g_flags[1] = b64;
    }
}

__global__ void k_zero_counts() {
    int i = blockIdx.x * blockDim.x + threadIdx.x;
    if (i < N_NODES) g_counts[i] = 0;
}

__global__ void k_hist(const void* ei) {
    int e = blockIdx.x * blockDim.x + threadIdx.x;
    if (e >= N_EDGES) return;
    int is64 = g_flags[0];
    int dst = ld_idx(ei, (long long)N_EDGES + e, is64);
    atomicAdd(&g_counts[dst], 1);
}

// inclusive scan of 1024-elem chunks
__global__ void k_scan1() {
    __shared__ int s[1024];
    int blk = blockIdx.x;
    int t = threadIdx.x;
    int idx = blk * 1024 + t;
    int v = (idx < N_NODES) ? g_counts[idx] : 0;
    s[t] = v;
    __syncthreads();
    for (int off = 1; off < 1024; off <<= 1) {
        int add = (t >= off) ? s[t - off] : 0;
        __syncthreads();
        s[t] += add;
        __syncthreads();
    }
    if (idx < N_NODES) g_rowptr[idx] = s[t];   // inclusive (temp)
    if (t == 1023) g_blocksums[blk] = s[t];
}

__global__ void k_scan2(int nblocks) {
    if (blockIdx.x == 0 && threadIdx.x == 0) {
        int acc = 0;
        for (int b = 0; b < nblocks; b++) {
            int v = g_blocksums[b];
            g_blocksums[b] = acc;
            acc += v;
        }
        g_rowptr[N_NODES] = N_EDGES;
    }
}

__global__ void k_scan3() {
    int i = blockIdx.x * blockDim.x + threadIdx.x;
    if (i < N_NODES) {
        int ex = g_rowptr[i] - g_counts[i] + g_blocksums[i >> 10];
        g_rowptr[i] = ex;
        g_wptr[i] = ex;
    }
}

__global__ void k_scatter(const void* ei) {
    int e = blockIdx.x * blockDim.x + threadIdx.x;
    if (e >= N_EDGES) return;
    int is64 = g_flags[0];
    int src = ld_idx(ei, e, is64);
    int dst = ld_idx(ei, (long long)N_EDGES + e, is64);
    int pos = atomicAdd(&g_wptr[dst], 1);
    g_esrc[pos] = src;
}

__global__ void k_copy4(const float4* __restrict__ src, float4* __restrict__ dst, int n4) {
    int i = blockIdx.x * blockDim.x + threadIdx.x;
    if (i < n4) dst[i] = src[i];
}

// one warp per node: agg[i] = sum over incoming edges of h[src]
__global__ void k_agg(const float* __restrict__ h, float* __restrict__ agg) {
    int warp = (blockIdx.x * blockDim.x + threadIdx.x) >> 5;
    int lane = threadIdx.x & 31;
    if (warp >= N_NODES) return;
    int s = g_rowptr[warp];
    int e = g_rowptr[warp + 1];
    float4 acc = make_float4(0.f, 0.f, 0.f, 0.f);
    for (int i = s; i < e; i++) {
        int src = g_esrc[i];
        float4 v = *(const float4*)&h[(long long)src * D + lane * 4];
        acc.x += v.x; acc.y += v.y; acc.z += v.z; acc.w += v.w;
    }
    *(float4*)&agg[(long long)warp * D + lane * 4] = acc;
}

// C[m,:] = relu(A1[m,:] @ W1 + A2[m,:] @ W2 + bias), W are 128x128 row-major (k-major)
__global__ __launch_bounds__(256, 2)
void k_gemm(const float* __restrict__ A1, const float* __restrict__ A2,
            const float* __restrict__ W1, const float* __restrict__ W2,
            const float* __restrict__ bias, float* __restrict__ C) {
    __shared__ float As[8][128];
    __shared__ float Bs[8][128];
    const int bm = blockIdx.x * 128;
    const int tid = threadIdx.x;
    const int tr = (tid >> 4) << 3;   // 0..120 step 8
    const int tc = (tid & 15) << 3;   // 0..120 step 8

    float acc[8][8];
#pragma unroll
    for (int i = 0; i < 8; i++)
#pragma unroll
        for (int j = 0; j < 8; j++) acc[i][j] = 0.f;

    const int ra = tid >> 1;          // row 0..127 of A tile
    const int ka = (tid & 1) * 4;     // k offset 0 or 4
    const int kb = tid >> 5;          // k 0..7 of B tile
    const int nb = (tid & 31) * 4;    // n 0..124

    for (int ph = 0; ph < 2; ph++) {
        const float* A = ph ? A2 : A1;
        const float* W = ph ? W2 : W1;
        for (int k0 = 0; k0 < 128; k0 += 8) {
            int row = bm + ra;
            float4 av = make_float4(0.f, 0.f, 0.f, 0.f);
            if (row < N_NODES)
                av = *(const float4*)&A[(long long)row * 128 + k0 + ka];
            As[ka + 0][ra] = av.x;
            As[ka + 1][ra] = av.y;
            As[ka + 2][ra] = av.z;
            As[ka + 3][ra] = av.w;
            float4 bv = *(const float4*)&W[(k0 + kb) * 128 + nb];
            *(float4*)&Bs[kb][nb] = bv;
            __syncthreads();
#pragma unroll
            for (int k = 0; k < 8; k++) {
                float ar[8], br[8];
                *(float4*)(ar)     = *(const float4*)&As[k][tr];
                *(float4*)(ar + 4) = *(const float4*)&As[k][tr + 4];
                *(float4*)(br)     = *(const float4*)&Bs[k][tc];
                *(float4*)(br + 4) = *(const float4*)&Bs[k][tc + 4];
#pragma unroll
                for (int i = 0; i < 8; i++)
#pragma unroll
                    for (int j = 0; j < 8; j++)
                        acc[i][j] += ar[i] * br[j];
            }
            __syncthreads();
        }
    }
#pragma unroll
    for (int i = 0; i < 8; i++) {
        int row = bm + tr + i;
        if (row < N_NODES) {
#pragma unroll
            for (int j = 0; j < 8; j += 4) {
                float4 o;
                o.x = fmaxf(acc[i][j + 0] + bias[tc + j + 0], 0.f);
                o.y = fmaxf(acc[i][j + 1] + bias[tc + j + 1], 0.f);
                o.z = fmaxf(acc[i][j + 2] + bias[tc + j + 2], 0.f);
                o.w = fmaxf(acc[i][j + 3] + bias[tc + j + 3], 0.f);
                *(float4*)&C[(long long)row * 128 + tc + j] = o;
            }
        }
    }
}

__global__ void k_zero_pool() {
    int i = blockIdx.x * blockDim.x + threadIdx.x;
    if (i < N_GRAPHS * D) g_pool[i] = 0.f;
    if (i < N_GRAPHS) g_cnt[i] = 0.f;
}

#define PCHUNK 256
__global__ void k_pool(const float* __restrict__ h, const void* bt) {
    int blk = blockIdx.x;
    int f = threadIdx.x;   // 128 threads, one per feature
    int start = blk * PCHUNK;
    if (start >= N_NODES) return;
    int end = start + PCHUNK;
    if (end > N_NODES) end = N_NODES;
    int is64 = g_flags[1];
    int cur = ld_idx(bt, start, is64);
    float s = 0.f, c = 0.f;
    for (int n = start; n < end; n++) {
        int g = ld_idx(bt, n, is64);
        if (g != cur) {
            atomicAdd(&g_pool[cur * D + f], s);
            if (f == 0) atomicAdd(&g_cnt[cur], c);
            s = 0.f; c = 0.f; cur = g;
        }
        s += h[(long long)n * D + f];
        c += 1.f;
    }
    atomicAdd(&g_pool[cur * D + f], s);
    if (f == 0) atomicAdd(&g_cnt[cur], c);
}

__global__ void k_snn1(const float* __restrict__ x, const float* __restrict__ w1,
                       const float* __restrict__ b1) {
    int g = blockIdx.x;
    int t = threadIdx.x;   // 256
    __shared__ float xs[SNN_IN];
    for (int i = t; i < SNN_IN; i += 256) xs[i] = x[g * SNN_IN + i];
    __syncthreads();
    for (int j = t; j < SNN_HID; j += 256) {
        float a = b1[j];
        for (int k = 0; k < SNN_IN; k++)
            a += xs[k] * w1[k * SNN_HID + j];
        g_snnh[g * SNN_HID + j] = fmaxf(a, 0.f);
    }
}

__global__ void k_final(const float* __restrict__ lin_w, const float* __restrict__ lin_b,
                        const float* __restrict__ w2, const float* __restrict__ b2,
                        const float* __restrict__ fuse_w, const float* __restrict__ fuse_b,
                        float* __restrict__ out) {
    int g = blockIdx.x;
    int t = threadIdx.x;   // 128
    __shared__ float mean[D];
    __shared__ float red[128];
    __shared__ float snl[N_CLASSES], gnl[N_CLASSES];
    float cnt = fmaxf(g_cnt[g], 1.f);
    mean[t] = g_pool[g * D + t] / cnt;
    __syncthreads();
    // gnn logits
    for (int c = 0; c < N_CLASSES; c++) {
        red[t] = mean[t] * lin_w[t * N_CLASSES + c];
        for (int off = 64; off > 0; off >>= 1) {
            __syncthreads();
            if (t < off) red[t] += red[t + off];
        }
        __syncthreads();
        if (t == 0) gnl[c] = red[0] + lin_b[c];
        __syncthreads();
    }
    // snn logits
    for (int c = 0; c < N_CLASSES; c++) {
        float p = 0.f;
        for (int k = t; k < SNN_HID; k += 128)
            p += g_snnh[g * SNN_HID + k] * w2[k * N_CLASSES + c];
        red[t] = p;
        for (int off = 64; off > 0; off >>= 1) {
            __syncthreads();
            if (t < off) red[t] += red[t + off];
        }
        __syncthreads();
        if (t == 0) snl[c] = SNN_BETA * (red[0] + b2[c]);
        __syncthreads();
    }
    if (t < N_CLASSES) {
        float o = fuse_b[t];
        for (int j = 0; j < N_CLASSES; j++) {
            o += snl[j] * fuse_w[j * N_CLASSES + t];
            o += gnl[j] * fuse_w[(N_CLASSES + j) * N_CLASSES + t];
        }
        out[g * N_CLASSES + t] = o;
    }
}

// ---------------- launch ----------------
extern "C" void kernel_launch(void* const* d_in, const int* in_sizes, int n_in,
                              void* d_out, int out_size) {
    const float* snn_x  = (const float*)d_in[0];
    const float* x      = (const float*)d_in[1];
    const void*  ei     = d_in[2];
    const void*  bt     = d_in[3];
    const float* snn_w1 = (const float*)d_in[4];
    const float* snn_b1 = (const float*)d_in[5];
    const float* snn_w2 = (const float*)d_in[6];
    const float* snn_b2 = (const float*)d_in[7];
    const float* wrel   = (const float*)d_in[8];
    const float* wroot  = (const float*)d_in[9];
    const float* brel   = (const float*)d_in[10];
    const float* lin_w  = (const float*)d_in[11];
    const float* lin_b  = (const float*)d_in[12];
    const float* fuse_w = (const float*)d_in[13];
    const float* fuse_b = (const float*)d_in[14];
    float* out = (float*)d_out;

    void* p;
    cudaGetSymbolAddress(&p, g_h0);  float* h0  = (float*)p;
    cudaGetSymbolAddress(&p, g_h1);  float* h1  = (float*)p;
    cudaGetSymbolAddress(&p, g_agg); float* agp = (float*)p;

    k_detect<<<1, 1>>>((const unsigned int*)ei, (const unsigned int*)bt);

    // CSR build (by dst)
    k_zero_counts<<<(N_NODES + 255) / 256, 256>>>();
    k_hist<<<(N_EDGES + 255) / 256, 256>>>(ei);
    const int nsb = (N_NODES + 1023) / 1024;   // 98
    k_scan1<<<nsb, 1024>>>();
    k_scan2<<<1, 1>>>(nsb);
    k_scan3<<<(N_NODES + 255) / 256, 256>>>();
    k_scatter<<<(N_EDGES + 255) / 256, 256>>>(ei);

    // h0 = x
    const int n4 = N_NODES * D / 4;
    k_copy4<<<(n4 + 255) / 256, 256>>>((const float4*)x, (float4*)h0, n4);

    // 7 GraphConv layers
    float* hin = h0;
    float* hout = h1;
    const int aggBlocks = (N_NODES * 32 + 255) / 256;
    const int gemmBlocks = (N_NODES + 127) / 128;
    for (int l = 0; l < N_LAYERS; l++) {
        k_agg<<<aggBlocks, 256>>>(hin, agp);
        k_gemm<<<gemmBlocks, 256>>>(agp, hin,
                                    wrel + (long long)l * D * D,
                                    wroot + (long long)l * D * D,
                                    brel + (long long)l * D, hout);
        float* tmp = hin; hin = hout; hout = tmp;
    }

    // global mean pool
    k_zero_pool<<<(N_GRAPHS * D + 255) / 256, 256>>>();
    k_pool<<<(N_NODES + PCHUNK - 1) / PCHUNK, 128>>>(hin, bt);

    // SNN + fusion
    k_snn1<<<N_GRAPHS, 256>>>(snn_x, snn_w1, snn_b1);
    k_final<<<N_GRAPHS, 128>>>(lin_w, lin_b, snn_w2, snn_b2, fuse_w, fuse_b, out);
}

// round 5
// speedup vs baseline: 1.1557x; 1.1557x over previous
#include <cuda_runtime.h>
#include <cstdint>

#define N_NODES  100000
#define N_EDGES  1600000
#define D        128
#define N_LAYERS 7
#define N_GRAPHS 64
#define N_CLASSES 10
#define SNN_IN   512
#define SNN_HID  1024
#define SNN_BETA 0.85f

// ---------------- scratch (no allocations allowed) ----------------
__device__ float g_h0[N_NODES * D];
__device__ float g_h1[N_NODES * D];
__device__ float g_agg[N_NODES * D];
__device__ int   g_counts[N_NODES];
__device__ int   g_rowptr[N_NODES + 1];
__device__ int   g_wptr[N_NODES];
__device__ int   g_esrc[N_EDGES];
__device__ int   g_blocksums[256];
__device__ float g_pool[N_GRAPHS * D];
__device__ float g_cnt[N_GRAPHS];
__device__ float g_snnh[N_GRAPHS * SNN_HID];
__device__ int   g_flags[2];   // [0]: edge_index is int64, [1]: batch is int64

// ---------------- portable tensor-core helpers (sm_80+ ISA only) ----------------
__device__ __forceinline__ uint32_t tf32_rna(float a) {
    uint32_t r;
    asm("cvt.rna.tf32.f32 %0, %1;" : "=r"(r) : "f"(a));
    return r;
}
// d += A(16x8,tf32) * B(8x8,tf32), fp32 accumulate
__device__ __forceinline__ void mma_tf32(float* d, const uint32_t* a, uint32_t b0, uint32_t b1) {
    asm volatile(
        "mma.sync.aligned.m16n8k8.row.col.f32.tf32.tf32.f32 "
        "{%0,%1,%2,%3}, {%4,%5,%6,%7}, {%8,%9}, {%0,%1,%2,%3};"
        : "+f"(d[0]), "+f"(d[1]), "+f"(d[2]), "+f"(d[3])
        : "r"(a[0]), "r"(a[1]), "r"(a[2]), "r"(a[3]), "r"(b0), "r"(b1));
}

// ---------------- index-width helpers ----------------
__device__ __forceinline__ int ld_idx(const void* p, long long i, int is64) {
    if (is64) return (int)((const long long*)p)[i];
    return ((const int*)p)[i];
}

__global__ void k_detect(const unsigned int* ei, const unsigned int* bt) {
    if (blockIdx.x == 0 && threadIdx.x == 0) {
        int e64 = 1;
        for (int i = 0; i < 1000; i++) if (ei[2 * i + 1] != 0u) { e64 = 0; break; }
        int b64 = 1;
        for (int i = 0; i < 500; i++) if (bt[99999 - 2 * i] != 0u) { b64 = 0; break; }
        g_flags[0] = e64;
        g_flags[1] = b64;
    }
}

// ---------------- CSR build ----------------
__global__ void k_zero_counts() {
    int i = blockIdx.x * blockDim.x + threadIdx.x;
    if (i < N_NODES) g_counts[i] = 0;
}
__global__ void k_hist(const void* ei) {
    int e = blockIdx.x * blockDim.x + threadIdx.x;
    if (e >= N_EDGES) return;
    int dst = ld_idx(ei, (long long)N_EDGES + e, g_flags[0]);
    atomicAdd(&g_counts[dst], 1);
}
__global__ void k_scan1() {
    __shared__ int s[1024];
    int blk = blockIdx.x, t = threadIdx.x;
    int idx = blk * 1024 + t;
    int v = (idx < N_NODES) ? g_counts[idx] : 0;
    s[t] = v;
    __syncthreads();
    for (int off = 1; off < 1024; off <<= 1) {
        int add = (t >= off) ? s[t - off] : 0;
        __syncthreads();
        s[t] += add;
        __syncthreads();
    }
    if (idx < N_NODES) g_rowptr[idx] = s[t];
    if (t == 1023) g_blocksums[blk] = s[t];
}
__global__ void k_scan2(int nblocks) {
    if (blockIdx.x == 0 && threadIdx.x == 0) {
        int acc = 0;
        for (int b = 0; b < nblocks; b++) { int v = g_blocksums[b]; g_blocksums[b] = acc; acc += v; }
        g_rowptr[N_NODES] = N_EDGES;
    }
}
__global__ void k_scan3() {
    int i = blockIdx.x * blockDim.x + threadIdx.x;
    if (i < N_NODES) {
        int ex = g_rowptr[i] - g_counts[i] + g_blocksums[i >> 10];
        g_rowptr[i] = ex;
        g_wptr[i] = ex;
    }
}
__global__ void k_scatter(const void* ei) {
    int e = blockIdx.x * blockDim.x + threadIdx.x;
    if (e >= N_EDGES) return;
    int is64 = g_flags[0];
    int src = ld_idx(ei, e, is64);
    int dst = ld_idx(ei, (long long)N_EDGES + e, is64);
    int pos = atomicAdd(&g_wptr[dst], 1);
    g_esrc[pos] = src;
}

// ---------------- aggregation: one warp per node ----------------
__global__ void k_agg(const float* __restrict__ h, float* __restrict__ agg) {
    int warp = (blockIdx.x * blockDim.x + threadIdx.x) >> 5;
    int lane = threadIdx.x & 31;
    if (warp >= N_NODES) return;
    int s = g_rowptr[warp];
    int e = g_rowptr[warp + 1];
    float4 acc = make_float4(0.f, 0.f, 0.f, 0.f);
    for (int i = s; i < e; i++) {
        int src = g_esrc[i];
        float4 v = *(const float4*)&h[(long long)src * D + lane * 4];
        acc.x += v.x; acc.y += v.y; acc.z += v.z; acc.w += v.w;
    }
    *(float4*)&agg[(long long)warp * D + lane * 4] = acc;
}

// ---------------- 3xTF32 mma.sync fused GraphConv GEMM ----------------
// C[m,:] = relu( A1[m,:] @ W1 + A2[m,:] @ W2 + bias )
// CTA tile: 128(M) x 128(N), K = 2 x 128 staged in 8 chunks of 32.
// SMEM strides chosen for conflict-free fragment loads:
//   A tiles stride 36 floats (bank = 4*row + col, all distinct per transaction)
//   B tiles stride 136 floats (bank = 8*k + n, all distinct)
#define ASTR 36
#define BSTR 136
#define OFF_AH 0
#define OFF_AL (128 * ASTR)                 // 4608
#define OFF_BH (2 * 128 * ASTR)             // 9216
#define OFF_BL (2 * 128 * ASTR + 32 * BSTR) // 13568
#define GEMM_SMEM_FLOATS (2 * 128 * ASTR + 2 * 32 * BSTR)  // 17920
#define GEMM_SMEM_BYTES (GEMM_SMEM_FLOATS * 4)             // 71680

__global__ __launch_bounds__(256, 1)
void k_gemm_mma(const float* __restrict__ A1, const float* __restrict__ A2,
                const float* __restrict__ W1, const float* __restrict__ W2,
                const float* __restrict__ bias, float* __restrict__ C) {
    extern __shared__ float sm[];
    float* Ah = sm + OFF_AH;
    float* Al = sm + OFF_AL;
    float* Bh = sm + OFF_BH;
    float* Bl = sm + OFF_BL;

    const int tid = threadIdx.x;
    const int w = tid >> 5;
    const int lane = tid & 31;
    const int g = lane >> 2;      // 0..7
    const int tg = lane & 3;      // 0..3
    const int bm = blockIdx.x * 128;
    const int mbase = (w & 3) * 32;   // warp M offset
    const int nbase = (w >> 2) * 64;  // warp N offset

    float acc[2][8][4];
#pragma unroll
    for (int mt = 0; mt < 2; mt++)
#pragma unroll
        for (int nt = 0; nt < 8; nt++)
#pragma unroll
            for (int q = 0; q < 4; q++) acc[mt][nt][q] = 0.f;

    for (int c = 0; c < 8; c++) {
        const float* A = (c < 4) ? A1 : A2;
        const float* W = (c < 4) ? W1 : W2;
        const int k0 = (c & 3) * 32;

        // ---- stage A chunk: 128 rows x 32 k, split hi/lo ----
#pragma unroll
        for (int it = 0; it < 4; it++) {
            int idx = it * 256 + tid;        // 0..1023 over (row, q) with q = k/4
            int row = idx >> 3;
            int q = idx & 7;
            float4 av = make_float4(0.f, 0.f, 0.f, 0.f);
            if (bm + row < N_NODES)
                av = *(const float4*)&A[(long long)(bm + row) * 128 + k0 + q * 4];
            float4 hv, lv;
            hv.x = __uint_as_float(tf32_rna(av.x)); lv.x = av.x - hv.x;
            hv.y = __uint_as_float(tf32_rna(av.y)); lv.y = av.y - hv.y;
            hv.z = __uint_as_float(tf32_rna(av.z)); lv.z = av.z - hv.z;
            hv.w = __uint_as_float(tf32_rna(av.w)); lv.w = av.w - hv.w;
            *(float4*)&Ah[row * ASTR + q * 4] = hv;
            *(float4*)&Al[row * ASTR + q * 4] = lv;
        }
        // ---- stage B chunk: 32 k x 128 n (W is [k][n] row-major), split hi/lo ----
#pragma unroll
        for (int it = 0; it < 4; it++) {
            int idx = it * 256 + tid;        // 0..1023 over (k, q) with q = n/4
            int k = idx >> 5;
            int q = idx & 31;
            float4 wv = *(const float4*)&W[(k0 + k) * 128 + q * 4];
            float4 hv, lv;
            hv.x = __uint_as_float(tf32_rna(wv.x)); lv.x = wv.x - hv.x;
            hv.y = __uint_as_float(tf32_rna(wv.y)); lv.y = wv.y - hv.y;
            hv.z = __uint_as_float(tf32_rna(wv.z)); lv.z = wv.z - hv.z;
            hv.w = __uint_as_float(tf32_rna(wv.w)); lv.w = wv.w - hv.w;
            *(float4*)&Bh[k * BSTR + q * 4] = hv;
            *(float4*)&Bl[k * BSTR + q * 4] = lv;
        }
        __syncthreads();

        // ---- compute: 4 k8-steps per chunk ----
#pragma unroll
        for (int ks = 0; ks < 4; ks++) {
            const int kk = ks * 8;
            uint32_t ah[2][4], al[2][4];
#pragma unroll
            for (int mt = 0; mt < 2; mt++) {
                int r0 = (mbase + mt * 16 + g) * ASTR + kk + tg;
                int r8 = r0 + 8 * ASTR;
                ah[mt][0] = __float_as_uint(Ah[r0]);
                ah[mt][1] = __float_as_uint(Ah[r8]);
                ah[mt][2] = __float_as_uint(Ah[r0 + 4]);
                ah[mt][3] = __float_as_uint(Ah[r8 + 4]);
                al[mt][0] = __float_as_uint(Al[r0]);
                al[mt][1] = __float_as_uint(Al[r8]);
                al[mt][2] = __float_as_uint(Al[r0 + 4]);
                al[mt][3] = __float_as_uint(Al[r8 + 4]);
            }
#pragma unroll
            for (int nt = 0; nt < 8; nt++) {
                int nn = nbase + nt * 8 + g;
                int kb0 = (kk + tg) * BSTR + nn;
                int kb4 = kb0 + 4 * BSTR;
                uint32_t bh0 = __float_as_uint(Bh[kb0]);
                uint32_t bh1 = __float_as_uint(Bh[kb4]);
                uint32_t bl0 = __float_as_uint(Bl[kb0]);
                uint32_t bl1 = __float_as_uint(Bl[kb4]);
#pragma unroll
                for (int mt = 0; mt < 2; mt++) {
                    mma_tf32(acc[mt][nt], ah[mt], bh0, bh1);
                    mma_tf32(acc[mt][nt], ah[mt], bl0, bl1);
                    mma_tf32(acc[mt][nt], al[mt], bh0, bh1);
                }
            }
        }
        __syncthreads();
    }

    // ---- epilogue: bias + relu, float2 stores ----
#pragma unroll
    for (int mt = 0; mt < 2; mt++) {
        int row0 = bm + mbase + mt * 16 + g;
        int row1 = row0 + 8;
#pragma unroll
        for (int nt = 0; nt < 8; nt++) {
            int col = nbase + nt * 8 + 2 * tg;
            float b0 = bias[col];
            float b1 = bias[col + 1];
            if (row0 < N_NODES) {
                float2 o;
                o.x = fmaxf(acc[mt][nt][0] + b0, 0.f);
                o.y = fmaxf(acc[mt][nt][1] + b1, 0.f);
                *(float2*)&C[(long long)row0 * 128 + col] = o;
            }
            if (row1 < N_NODES) {
                float2 o;
                o.x = fmaxf(acc[mt][nt][2] + b0, 0.f);
                o.y = fmaxf(acc[mt][nt][3] + b1, 0.f);
                *(float2*)&C[(long long)row1 * 128 + col] = o;
            }
        }
    }
}

// ---------------- pooling / SNN / fusion ----------------
__global__ void k_zero_pool() {
    int i = blockIdx.x * blockDim.x + threadIdx.x;
    if (i < N_GRAPHS * D) g_pool[i] = 0.f;
    if (i < N_GRAPHS) g_cnt[i] = 0.f;
}

#define PCHUNK 256
__global__ void k_pool(const float* __restrict__ h, const void* bt) {
    int blk = blockIdx.x;
    int f = threadIdx.x;
    int start = blk * PCHUNK;
    if (start >= N_NODES) return;
    int end = start + PCHUNK;
    if (end > N_NODES) end = N_NODES;
    int is64 = g_flags[1];
    int cur = ld_idx(bt, start, is64);
    float s = 0.f, c = 0.f;
    for (int n = start; n < end; n++) {
        int g = ld_idx(bt, n, is64);
        if (g != cur) {
            atomicAdd(&g_pool[cur * D + f], s);
            if (f == 0) atomicAdd(&g_cnt[cur], c);
            s = 0.f; c = 0.f; cur = g;
        }
        s += h[(long long)n * D + f];
        c += 1.f;
    }
    atomicAdd(&g_pool[cur * D + f], s);
    if (f == 0) atomicAdd(&g_cnt[cur], c);
}

__global__ void k_snn1(const float* __restrict__ x, const float* __restrict__ w1,
                       const float* __restrict__ b1) {
    int g = blockIdx.x;
    int t = threadIdx.x;   // 256
    __shared__ float xs[SNN_IN];
    for (int i = t; i < SNN_IN; i += 256) xs[i] = x[g * SNN_IN + i];
    __syncthreads();
    for (int j = t; j < SNN_HID; j += 256) {
        float a = b1[j];
        for (int k = 0; k < SNN_IN; k++)
            a += xs[k] * w1[k * SNN_HID + j];
        g_snnh[g * SNN_HID + j] = fmaxf(a, 0.f);
    }
}

__global__ void k_final(const float* __restrict__ lin_w, const float* __restrict__ lin_b,
                        const float* __restrict__ w2, const float* __restrict__ b2,
                        const float* __restrict__ fuse_w, const float* __restrict__ fuse_b,
                        float* __restrict__ out) {
    int g = blockIdx.x;
    int t = threadIdx.x;   // 128
    __shared__ float mean[D];
    __shared__ float red[128];
    __shared__ float snl[N_CLASSES], gnl[N_CLASSES];
    float cnt = fmaxf(g_cnt[g], 1.f);
    mean[t] = g_pool[g * D + t] / cnt;
    __syncthreads();
    for (int c = 0; c < N_CLASSES; c++) {
        red[t] = mean[t] * lin_w[t * N_CLASSES + c];
        for (int off = 64; off > 0; off >>= 1) {
            __syncthreads();
            if (t < off) red[t] += red[t + off];
        }
        __syncthreads();
        if (t == 0) gnl[c] = red[0] + lin_b[c];
        __syncthreads();
    }
    for (int c = 0; c < N_CLASSES; c++) {
        float p = 0.f;
        for (int k = t; k < SNN_HID; k += 128)
            p += g_snnh[g * SNN_HID + k] * w2[k * N_CLASSES + c];
        red[t] = p;
        for (int off = 64; off > 0; off >>= 1) {
            __syncthreads();
            if (t < off) red[t] += red[t + off];
        }
        __syncthreads();
        if (t == 0) snl[c] = SNN_BETA * (red[0] + b2[c]);
        __syncthreads();
    }
    if (t < N_CLASSES) {
        float o = fuse_b[t];
        for (int j = 0; j < N_CLASSES; j++) {
            o += snl[j] * fuse_w[j * N_CLASSES + t];
            o += gnl[j] * fuse_w[(N_CLASSES + j) * N_CLASSES + t];
        }
        out[g * N_CLASSES + t] = o;
    }
}

// ---------------- launch ----------------
extern "C" void kernel_launch(void* const* d_in, const int* in_sizes, int n_in,
                              void* d_out, int out_size) {
    const float* snn_x  = (const float*)d_in[0];
    const float* x      = (const float*)d_in[1];
    const void*  ei     = d_in[2];
    const void*  bt     = d_in[3];
    const float* snn_w1 = (const float*)d_in[4];
    const float* snn_b1 = (const float*)d_in[5];
    const float* snn_w2 = (const float*)d_in[6];
    const float* snn_b2 = (const float*)d_in[7];
    const float* wrel   = (const float*)d_in[8];
    const float* wroot  = (const float*)d_in[9];
    const float* brel   = (const float*)d_in[10];
    const float* lin_w  = (const float*)d_in[11];
    const float* lin_b  = (const float*)d_in[12];
    const float* fuse_w = (const float*)d_in[13];
    const float* fuse_b = (const float*)d_in[14];
    float* out = (float*)d_out;

    void* p;
    cudaGetSymbolAddress(&p, g_h0);  float* h0  = (float*)p;
    cudaGetSymbolAddress(&p, g_h1);  float* h1  = (float*)p;
    cudaGetSymbolAddress(&p, g_agg); float* agp = (float*)p;

    static int smem_set = 0;
    if (!smem_set) {
        cudaFuncSetAttribute(k_gemm_mma, cudaFuncAttributeMaxDynamicSharedMemorySize, GEMM_SMEM_BYTES);
        smem_set = 1;
    }

    k_detect<<<1, 1>>>((const unsigned int*)ei, (const unsigned int*)bt);

    // CSR build (by dst)
    k_zero_counts<<<(N_NODES + 255) / 256, 256>>>();
    k_hist<<<(N_EDGES + 255) / 256, 256>>>(ei);
    const int nsb = (N_NODES + 1023) / 1024;   // 98
    k_scan1<<<nsb, 1024>>>();
    k_scan2<<<1, 1>>>(nsb);
    k_scan3<<<(N_NODES + 255) / 256, 256>>>();
    k_scatter<<<(N_EDGES + 255) / 256, 256>>>(ei);

    // 7 GraphConv layers; layer 0 consumes x directly (no copy)
    const float* hin = x;
    float* hout = h1;
    const int aggBlocks = (N_NODES * 32 + 255) / 256;
    const int gemmBlocks = (N_NODES + 127) / 128;   // 782
    for (int l = 0; l < N_LAYERS; l++) {
        k_agg<<<aggBlocks, 256>>>(hin, agp);
        k_gemm_mma<<<gemmBlocks, 256, GEMM_SMEM_BYTES>>>(agp, hin,
                                                         wrel + (long long)l * D * D,
                                                         wroot + (long long)l * D * D,
                                                         brel + (long long)l * D, hout);
        hin = hout;
        hout = (hout == h1) ? h0 : h1;
    }

    // global mean pool
    k_zero_pool<<<(N_GRAPHS * D + 255) / 256, 256>>>();
    k_pool<<<(N_NODES + PCHUNK - 1) / PCHUNK, 128>>>(hin, bt);

    // SNN + fusion
    k_snn1<<<N_GRAPHS, 256>>>(snn_x, snn_w1, snn_b1);
    k_final<<<N_GRAPHS, 128>>>(lin_w, lin_b, snn_w2, snn_b2, fuse_w, fuse_b, out);
}

// round 6
// speedup vs baseline: 1.2465x; 1.0786x over previous
#include <cuda_runtime.h>
#include <cstdint>

#define N_NODES  100000
#define N_EDGES  1600000
#define D        128
#define N_LAYERS 7
#define N_GRAPHS 64
#define N_CLASSES 10
#define SNN_IN   512
#define SNN_HID  1024
#define SNN_BETA 0.85f

// ---------------- scratch (no allocations allowed) ----------------
__device__ float g_h0[N_NODES * D];
__device__ float g_h1[N_NODES * D];
__device__ float g_agg[N_NODES * D];
__device__ int   g_counts[N_NODES];
__device__ int   g_rowptr[N_NODES + 1];
__device__ int   g_wptr[N_NODES];
__device__ int   g_esrc[N_EDGES];
__device__ int   g_blocksums[256];
__device__ float g_pool[N_GRAPHS * D];
__device__ float g_cnt[N_GRAPHS];
__device__ float g_snnh[N_GRAPHS * SNN_HID];
__device__ int   g_flags[2];   // [0]: edge_index is int64, [1]: batch is int64
// per-layer transposed + hi/lo split weights: [l][mat][part][n][k]
__device__ float g_wsplit[N_LAYERS * 4 * D * D];

// ---------------- portable tensor-core helpers (sm_80+ ISA only) ----------------
__device__ __forceinline__ uint32_t tf32_rna(float a) {
    uint32_t r;
    asm("cvt.rna.tf32.f32 %0, %1;" : "=r"(r) : "f"(a));
    return r;
}
__device__ __forceinline__ void mma_tf32(float* d, const uint32_t* a, uint32_t b0, uint32_t b1) {
    asm volatile(
        "mma.sync.aligned.m16n8k8.row.col.f32.tf32.tf32.f32 "
        "{%0,%1,%2,%3}, {%4,%5,%6,%7}, {%8,%9}, {%0,%1,%2,%3};"
        : "+f"(d[0]), "+f"(d[1]), "+f"(d[2]), "+f"(d[3])
        : "r"(a[0]), "r"(a[1]), "r"(a[2]), "r"(a[3]), "r"(b0), "r"(b1));
}
__device__ __forceinline__ void ldsm_x4(uint32_t* r, uint32_t addr) {
    asm volatile("ldmatrix.sync.aligned.m8n8.x4.shared.b16 {%0,%1,%2,%3}, [%4];"
        : "=r"(r[0]), "=r"(r[1]), "=r"(r[2]), "=r"(r[3]) : "r"(addr));
}
__device__ __forceinline__ void ldsm_x2(uint32_t* r, uint32_t addr) {
    asm volatile("ldmatrix.sync.aligned.m8n8.x2.shared.b16 {%0,%1}, [%2];"
        : "=r"(r[0]), "=r"(r[1]) : "r"(addr));
}
__device__ __forceinline__ uint32_t smem_u32(const void* p) {
    uint32_t a;
    asm("{ .reg .u64 t; cvta.to.shared.u64 t, %1; cvt.u32.u64 %0, t; }" : "=r"(a) : "l"(p));
    return a;
}

// ---------------- index-width helpers ----------------
__device__ __forceinline__ int ld_idx(const void* p, long long i, int is64) {
    if (is64) return (int)((const long long*)p)[i];
    return ((const int*)p)[i];
}

// Parallel dtype detection: one load per thread, benign shared-write race.
__global__ void k_detect(const unsigned int* ei, const unsigned int* bt) {
    __shared__ int e64s, b64s;
    int t = threadIdx.x;   // 256
    if (t == 0) { e64s = 1; b64s = 1; }
    __syncthreads();
    if (ei[2 * t + 1] != 0u) e64s = 0;          // odd words: int64 high words (0) or int32 data
    if (bt[99999 - 2 * t] != 0u) b64s = 0;      // odd words near tail: int64 high (0) or ids ~63
    __syncthreads();
    if (t == 0) { g_flags[0] = e64s; g_flags[1] = b64s; }
}

// Transpose + tf32 hi/lo split of all layer weights (once per launch).
__global__ void k_wprep(const float* __restrict__ wrel, const float* __restrict__ wroot) {
    int idx = blockIdx.x * 256 + threadIdx.x;
    if (idx >= N_LAYERS * D * D) return;
    int l = idx / (D * D);
    int r = idx % (D * D);
    int k = r / D;
    int n = r % D;
    float a = wrel[(long long)l * D * D + k * D + n];
    float ah = __uint_as_float(tf32_rna(a));
    g_wsplit[(l * 4 + 0) * D * D + n * D + k] = ah;
    g_wsplit[(l * 4 + 1) * D * D + n * D + k] = a - ah;
    float b = wroot[(long long)l * D * D + k * D + n];
    float bh = __uint_as_float(tf32_rna(b));
    g_wsplit[(l * 4 + 2) * D * D + n * D + k] = bh;
    g_wsplit[(l * 4 + 3) * D * D + n * D + k] = b - bh;
}

// ---------------- CSR build ----------------
__global__ void k_zero_counts() {
    int i = blockIdx.x * blockDim.x + threadIdx.x;
    if (i < N_NODES) g_counts[i] = 0;
}
__global__ void k_hist(const void* ei) {
    int e = blockIdx.x * blockDim.x + threadIdx.x;
    if (e >= N_EDGES) return;
    int dst = ld_idx(ei, (long long)N_EDGES + e, g_flags[0]);
    atomicAdd(&g_counts[dst], 1);
}
__global__ void k_scan1() {
    __shared__ int s[1024];
    int blk = blockIdx.x, t = threadIdx.x;
    int idx = blk * 1024 + t;
    int v = (idx < N_NODES) ? g_counts[idx] : 0;
    s[t] = v;
    __syncthreads();
    for (int off = 1; off < 1024; off <<= 1) {
        int add = (t >= off) ? s[t - off] : 0;
        __syncthreads();
        s[t] += add;
        __syncthreads();
    }
    if (idx < N_NODES) g_rowptr[idx] = s[t];
    if (t == 1023) g_blocksums[blk] = s[t];
}
__global__ void k_scan2(int nblocks) {
    if (blockIdx.x == 0 && threadIdx.x == 0) {
        int acc = 0;
        for (int b = 0; b < nblocks; b++) { int v = g_blocksums[b]; g_blocksums[b] = acc; acc += v; }
        g_rowptr[N_NODES] = N_EDGES;
    }
}
__global__ void k_scan3() {
    int i = blockIdx.x * blockDim.x + threadIdx.x;
    if (i < N_NODES) {
        int ex = g_rowptr[i] - g_counts[i] + g_blocksums[i >> 10];
        g_rowptr[i] = ex;
        g_wptr[i] = ex;
    }
}
__global__ void k_scatter(const void* ei) {
    int e = blockIdx.x * blockDim.x + threadIdx.x;
    if (e >= N_EDGES) return;
    int is64 = g_flags[0];
    int src = ld_idx(ei, e, is64);
    int dst = ld_idx(ei, (long long)N_EDGES + e, is64);
    int pos = atomicAdd(&g_wptr[dst], 1);
    g_esrc[pos] = src;
}

// ---------------- aggregation: one warp per node ----------------
__global__ void k_agg(const float* __restrict__ h, float* __restrict__ agg) {
    int warp = (blockIdx.x * blockDim.x + threadIdx.x) >> 5;
    int lane = threadIdx.x & 31;
    if (warp >= N_NODES) return;
    int s = g_rowptr[warp];
    int e = g_rowptr[warp + 1];
    float4 acc = make_float4(0.f, 0.f, 0.f, 0.f);
    for (int i = s; i < e; i++) {
        int src = g_esrc[i];
        float4 v = *(const float4*)&h[(long long)src * D + lane * 4];
        acc.x += v.x; acc.y += v.y; acc.z += v.z; acc.w += v.w;
    }
    *(float4*)&agg[(long long)warp * D + lane * 4] = acc;
}

// ---------------- 3xTF32 mma.sync GraphConv GEMM (ldmatrix + pipelined staging) ----
// C[m,:] = relu( A1[m,:] @ W1 + A2[m,:] @ W2 + bias )
// CTA tile 128x128; K = 2x128 in 8 chunks of 32. SMEM layout: plain [row][k],
// row stride 36 floats (ldmatrix + STS.128 conflict-free).
#define ASTR 36
#define SM_AH 0
#define SM_AL 18432
#define SM_BH 36864
#define SM_BL 55296
#define GEMM_SMEM_BYTES 73728

__global__ __launch_bounds__(256, 1)
void k_gemm_mma(const float* __restrict__ A1, const float* __restrict__ A2,
                const float* __restrict__ Wt,   // this layer's 4*16384 split/transposed
                const float* __restrict__ bias, float* __restrict__ C) {
    extern __shared__ float smf[];
    char* smc = (char*)smf;
    const uint32_t sbase = smem_u32(smf);
    const int tid = threadIdx.x;
    const int w = tid >> 5;
    const int lane = tid & 31;
    const int g = lane >> 2;
    const int tg = lane & 3;
    const int bm = blockIdx.x * 128;
    const int mbase = (w & 3) * 32;
    const int nbase = (w >> 2) * 64;

    float acc[2][8][4];
#pragma unroll
    for (int mt = 0; mt < 2; mt++)
#pragma unroll
        for (int nt = 0; nt < 8; nt++)
#pragma unroll
            for (int q = 0; q < 4; q++) acc[mt][nt][q] = 0.f;

    // per-thread staging indices (same for A and B)
    const int srow = tid >> 3;          // stepped by 32 per it
    const int sq = tid & 7;             // k-quad 0..7

    // prefetch chunk 0's A into registers
    float4 pa[4];
#pragma unroll
    for (int it = 0; it < 4; it++) {
        int row = it * 32 + srow;
        pa[it] = (bm + row < N_NODES)
                 ? *(const float4*)&A1[(long long)(bm + row) * 128 + sq * 4]
                 : make_float4(0.f, 0.f, 0.f, 0.f);
    }

    // ldmatrix lane addressing
    const int aSel = lane >> 3;                       // 0..3
    const int aRow = (lane & 7) + (aSel & 1) * 8;     // row within 16
    const uint32_t aKoff = (aSel >> 1) * 16;          // +4 floats for m2/m3
    const int bRow = lane & 7;
    const uint32_t bKoff = ((lane >> 3) & 1) * 16;    // +4 floats for m1

    for (int c = 0; c < 8; c++) {
        const int k0 = (c & 3) * 32;
        const float* wh = Wt + ((c >> 2) * 2) * (D * D);
        const float* wl = wh + D * D;

        // ---- store staged A (split hi/lo) + load/store B chunk ----
#pragma unroll
        for (int it = 0; it < 4; it++) {
            int row = it * 32 + srow;
            uint32_t off = (uint32_t)(row * ASTR + sq * 4) * 4u;
            float4 v = pa[it];
            float4 hv, lv;
            hv.x = __uint_as_float(tf32_rna(v.x)); lv.x = v.x - hv.x;
            hv.y = __uint_as_float(tf32_rna(v.y)); lv.y = v.y - hv.y;
            hv.z = __uint_as_float(tf32_rna(v.z)); lv.z = v.z - hv.z;
            hv.w = __uint_as_float(tf32_rna(v.w)); lv.w = v.w - hv.w;
            *(float4*)(smc + SM_AH + off) = hv;
            *(float4*)(smc + SM_AL + off) = lv;
            // B: Wt already transposed+split; coalesced float4 loads
            *(float4*)(smc + SM_BH + off) = *(const float4*)&wh[row * 128 + k0 + sq * 4];
            *(float4*)(smc + SM_BL + off) = *(const float4*)&wl[row * 128 + k0 + sq * 4];
        }
        __syncthreads();

        // ---- prefetch next chunk's A into registers (overlaps with compute) ----
        if (c < 7) {
            const float* An = ((c + 1) < 4) ? A1 : A2;
            const int k0n = ((c + 1) & 3) * 32;
#pragma unroll
            for (int it = 0; it < 4; it++) {
                int row = it * 32 + srow;
                pa[it] = (bm + row < N_NODES)
                         ? *(const float4*)&An[(long long)(bm + row) * 128 + k0n + sq * 4]
                         : make_float4(0.f, 0.f, 0.f, 0.f);
            }
        }

        // ---- A fragments for the whole chunk via ldmatrix.x4 ----
        uint32_t ah[2][4][4], al[2][4][4];
#pragma unroll
        for (int mt = 0; mt < 2; mt++) {
            uint32_t base = sbase + (uint32_t)((mbase + mt * 16 + aRow) * ASTR) * 4u + aKoff;
#pragma unroll
            for (int ks = 0; ks < 4; ks++) {
                ldsm_x4(ah[mt][ks], base + SM_AH + 32u * ks);
                ldsm_x4(al[mt][ks], base + SM_AL + 32u * ks);
            }
        }

        // ---- B fragments + mma ----
#pragma unroll
        for (int nt = 0; nt < 8; nt++) {
            uint32_t bb = sbase + (uint32_t)((nbase + nt * 8 + bRow) * ASTR) * 4u + bKoff;
#pragma unroll
            for (int ks = 0; ks < 4; ks++) {
                uint32_t bh[2], bl[2];
                ldsm_x2(bh, bb + SM_BH + 32u * ks);
                ldsm_x2(bl, bb + SM_BL + 32u * ks);
#pragma unroll
                for (int mt = 0; mt < 2; mt++) {
                    mma_tf32(acc[mt][nt], ah[mt][ks], bh[0], bh[1]);
                    mma_tf32(acc[mt][nt], ah[mt][ks], bl[0], bl[1]);
                    mma_tf32(acc[mt][nt], al[mt][ks], bh[0], bh[1]);
                }
            }
        }
        __syncthreads();
    }

    // ---- epilogue: bias + relu, float2 stores ----
#pragma unroll
    for (int mt = 0; mt < 2; mt++) {
        int row0 = bm + mbase + mt * 16 + g;
        int row1 = row0 + 8;
#pragma unroll
        for (int nt = 0; nt < 8; nt++) {
            int col = nbase + nt * 8 + 2 * tg;
            float b0 = bias[col];
            float b1 = bias[col + 1];
            if (row0 < N_NODES) {
                float2 o;
                o.x = fmaxf(acc[mt][nt][0] + b0, 0.f);
                o.y = fmaxf(acc[mt][nt][1] + b1, 0.f);
                *(float2*)&C[(long long)row0 * 128 + col] = o;
            }
            if (row1 < N_NODES) {
                float2 o;
                o.x = fmaxf(acc[mt][nt][2] + b0, 0.f);
                o.y = fmaxf(acc[mt][nt][3] + b1, 0.f);
                *(float2*)&C[(long long)row1 * 128 + col] = o;
            }
        }
    }
}

// ---------------- pooling / SNN / fusion ----------------
__global__ void k_zero_pool() {
    int i = blockIdx.x * blockDim.x + threadIdx.x;
    if (i < N_GRAPHS * D) g_pool[i] = 0.f;
    if (i < N_GRAPHS) g_cnt[i] = 0.f;
}

#define PCHUNK 256
__global__ void k_pool(const float* __restrict__ h, const void* bt) {
    int blk = blockIdx.x;
    int f = threadIdx.x;
    int start = blk * PCHUNK;
    if (start >= N_NODES) return;
    int end = start + PCHUNK;
    if (end > N_NODES) end = N_NODES;
    int is64 = g_flags[1];
    int cur = ld_idx(bt, start, is64);
    float s = 0.f, c = 0.f;
    for (int n = start; n < end; n++) {
        int g = ld_idx(bt, n, is64);
        if (g != cur) {
            atomicAdd(&g_pool[cur * D + f], s);
            if (f == 0) atomicAdd(&g_cnt[cur], c);
            s = 0.f; c = 0.f; cur = g;
        }
        s += h[(long long)n * D + f];
        c += 1.f;
    }
    atomicAdd(&g_pool[cur * D + f], s);
    if (f == 0) atomicAdd(&g_cnt[cur], c);
}

__global__ void k_snn1(const float* __restrict__ x, const float* __restrict__ w1,
                       const float* __restrict__ b1) {
    int g = blockIdx.x;
    int t = threadIdx.x;   // 256
    __shared__ float xs[SNN_IN];
    for (int i = t; i < SNN_IN; i += 256) xs[i] = x[g * SNN_IN + i];
    __syncthreads();
    for (int j = t; j < SNN_HID; j += 256) {
        float a = b1[j];
        for (int k = 0; k < SNN_IN; k++)
            a += xs[k] * w1[k * SNN_HID + j];
        g_snnh[g * SNN_HID + j] = fmaxf(a, 0.f);
    }
}

__global__ void k_final(const float* __restrict__ lin_w, const float* __restrict__ lin_b,
                        const float* __restrict__ w2, const float* __restrict__ b2,
                        const float* __restrict__ fuse_w, const float* __restrict__ fuse_b,
                        float* __restrict__ out) {
    int g = blockIdx.x;
    int t = threadIdx.x;   // 128
    __shared__ float mean[D];
    __shared__ float red[128];
    __shared__ float snl[N_CLASSES], gnl[N_CLASSES];
    float cnt = fmaxf(g_cnt[g], 1.f);
    mean[t] = g_pool[g * D + t] / cnt;
    __syncthreads();
    for (int c = 0; c < N_CLASSES; c++) {
        red[t] = mean[t] * lin_w[t * N_CLASSES + c];
        for (int off = 64; off > 0; off >>= 1) {
            __syncthreads();
            if (t < off) red[t] += red[t + off];
        }
        __syncthreads();
        if (t == 0) gnl[c] = red[0] + lin_b[c];
        __syncthreads();
    }
    for (int c = 0; c < N_CLASSES; c++) {
        float p = 0.f;
        for (int k = t; k < SNN_HID; k += 128)
            p += g_snnh[g * SNN_HID + k] * w2[k * N_CLASSES + c];
        red[t] = p;
        for (int off = 64; off > 0; off >>= 1) {
            __syncthreads();
            if (t < off) red[t] += red[t + off];
        }
        __syncthreads();
        if (t == 0) snl[c] = SNN_BETA * (red[0] + b2[c]);
        __syncthreads();
    }
    if (t < N_CLASSES) {
        float o = fuse_b[t];
        for (int j = 0; j < N_CLASSES; j++) {
            o += snl[j] * fuse_w[j * N_CLASSES + t];
            o += gnl[j] * fuse_w[(N_CLASSES + j) * N_CLASSES + t];
        }
        out[g * N_CLASSES + t] = o;
    }
}

// ---------------- launch ----------------
extern "C" void kernel_launch(void* const* d_in, const int* in_sizes, int n_in,
                              void* d_out, int out_size) {
    const float* snn_x  = (const float*)d_in[0];
    const float* x      = (const float*)d_in[1];
    const void*  ei     = d_in[2];
    const void*  bt     = d_in[3];
    const float* snn_w1 = (const float*)d_in[4];
    const float* snn_b1 = (const float*)d_in[5];
    const float* snn_w2 = (const float*)d_in[6];
    const float* snn_b2 = (const float*)d_in[7];
    const float* wrel   = (const float*)d_in[8];
    const float* wroot  = (const float*)d_in[9];
    const float* brel   = (const float*)d_in[10];
    const float* lin_w  = (const float*)d_in[11];
    const float* lin_b  = (const float*)d_in[12];
    const float* fuse_w = (const float*)d_in[13];
    const float* fuse_b = (const float*)d_in[14];
    float* out = (float*)d_out;

    void* p;
    cudaGetSymbolAddress(&p, g_h0);     float* h0  = (float*)p;
    cudaGetSymbolAddress(&p, g_h1);     float* h1  = (float*)p;
    cudaGetSymbolAddress(&p, g_agg);    float* agp = (float*)p;
    cudaGetSymbolAddress(&p, g_wsplit); float* wsp = (float*)p;

    static int smem_set = 0;
    if (!smem_set) {
        cudaFuncSetAttribute(k_gemm_mma, cudaFuncAttributeMaxDynamicSharedMemorySize, GEMM_SMEM_BYTES);
        smem_set = 1;
    }

    k_detect<<<1, 256>>>((const unsigned int*)ei, (const unsigned int*)bt);
    k_wprep<<<(N_LAYERS * D * D + 255) / 256, 256>>>(wrel, wroot);

    // CSR build (by dst)
    k_zero_counts<<<(N_NODES + 255) / 256, 256>>>();
    k_hist<<<(N_EDGES + 255) / 256, 256>>>(ei);
    const int nsb = (N_NODES + 1023) / 1024;   // 98
    k_scan1<<<nsb, 1024>>>();
    k_scan2<<<1, 1>>>(nsb);
    k_scan3<<<(N_NODES + 255) / 256, 256>>>();
    k_scatter<<<(N_EDGES + 255) / 256, 256>>>(ei);

    // 7 GraphConv layers; layer 0 consumes x directly
    const float* hin = x;
    float* hout = h1;
    const int aggBlocks = (N_NODES * 32 + 255) / 256;
    const int gemmBlocks = (N_NODES + 127) / 128;   // 782
    for (int l = 0; l < N_LAYERS; l++) {
        k_agg<<<aggBlocks, 256>>>(hin, agp);
        k_gemm_mma<<<gemmBlocks, 256, GEMM_SMEM_BYTES>>>(agp, hin,
                                                         wsp + (long long)l * 4 * D * D,
                                                         brel + (long long)l * D, hout);
        hin = hout;
        hout = (hout == h1) ? h0 : h1;
    }

    // global mean pool
    k_zero_pool<<<(N_GRAPHS * D + 255) / 256, 256>>>();
    k_pool<<<(N_NODES + PCHUNK - 1) / PCHUNK, 128>>>(hin, bt);

    // SNN + fusion
    k_snn1<<<N_GRAPHS, 256>>>(snn_x, snn_w1, snn_b1);
    k_final<<<N_GRAPHS, 128>>>(lin_w, lin_b, snn_w2, snn_b2, fuse_w, fuse_b, out);
}

// round 7
// speedup vs baseline: 1.6040x; 1.2868x over previous
#include <cuda_runtime.h>
#include <cstdint>

#define N_NODES  100000
#define N_EDGES  1600000
#define D        128
#define N_LAYERS 7
#define N_GRAPHS 64
#define N_CLASSES 10
#define SNN_IN   512
#define SNN_HID  1024
#define SNN_BETA 0.85f

// ---------------- scratch (no allocations allowed) ----------------
__device__ float g_h0[N_NODES * D];
__device__ float g_h1[N_NODES * D];
__device__ float g_agg[N_NODES * D];
__device__ int   g_counts[N_NODES];
__device__ int   g_rowptr[N_NODES + 1];
__device__ int   g_wptr[N_NODES];
__device__ int   g_esrc[N_EDGES];
__device__ int   g_blocksums[256];
__device__ float g_pool[N_GRAPHS * D];
__device__ float g_cnt[N_GRAPHS];
__device__ float g_snnh[N_GRAPHS * SNN_HID];
__device__ int   g_flags[2];   // [0]: edge_index is int64, [1]: batch is int64
// packed bf16x2 split weights: [l][mat][part][n][kword]  (2 k per word)
__device__ uint32_t g_wsp[N_LAYERS * 2 * 2 * D * (D / 2)];

// ---------------- portable tensor-core helpers (sm_80+ ISA only) ----------------
__device__ __forceinline__ uint32_t pack_bf16(float lo, float hi) {
    uint32_t r;
    asm("cvt.rn.bf16x2.f32 %0, %1, %2;" : "=r"(r) : "f"(hi), "f"(lo));
    return r;
}
__device__ __forceinline__ void mma_bf16(float* d, const uint32_t* a, uint32_t b0, uint32_t b1) {
    asm volatile(
        "mma.sync.aligned.m16n8k16.row.col.f32.bf16.bf16.f32 "
        "{%0,%1,%2,%3}, {%4,%5,%6,%7}, {%8,%9}, {%0,%1,%2,%3};"
        : "+f"(d[0]), "+f"(d[1]), "+f"(d[2]), "+f"(d[3])
        : "r"(a[0]), "r"(a[1]), "r"(a[2]), "r"(a[3]), "r"(b0), "r"(b1));
}
__device__ __forceinline__ void ldsm_x4(uint32_t* r, uint32_t addr) {
    asm volatile("ldmatrix.sync.aligned.m8n8.x4.shared.b16 {%0,%1,%2,%3}, [%4];"
        : "=r"(r[0]), "=r"(r[1]), "=r"(r[2]), "=r"(r[3]) : "r"(addr));
}
__device__ __forceinline__ void ldsm_x2(uint32_t* r, uint32_t addr) {
    asm volatile("ldmatrix.sync.aligned.m8n8.x2.shared.b16 {%0,%1}, [%2];"
        : "=r"(r[0]), "=r"(r[1]) : "r"(addr));
}
__device__ __forceinline__ uint32_t smem_u32(const void* p) {
    uint32_t a;
    asm("{ .reg .u64 t; cvta.to.shared.u64 t, %1; cvt.u32.u64 %0, t; }" : "=r"(a) : "l"(p));
    return a;
}
// split two floats into packed bf16 hi word + residual lo word
__device__ __forceinline__ void split2(float f0, float f1, uint32_t& hw, uint32_t& lw) {
    hw = pack_bf16(f0, f1);
    float f0h = __uint_as_float(hw << 16);
    float f1h = __uint_as_float(hw & 0xFFFF0000u);
    lw = pack_bf16(f0 - f0h, f1 - f1h);
}

// ---------------- index-width helpers ----------------
__device__ __forceinline__ int ld_idx(const void* p, long long i, int is64) {
    if (is64) return (int)((const long long*)p)[i];
    return ((const int*)p)[i];
}

// Parallel dtype detection: one load per thread, benign shared-write race.
__global__ void k_detect(const unsigned int* ei, const unsigned int* bt) {
    __shared__ int e64s, b64s;
    int t = threadIdx.x;   // 256
    if (t == 0) { e64s = 1; b64s = 1; }
    __syncthreads();
    if (ei[2 * t + 1] != 0u) e64s = 0;
    if (bt[99999 - 2 * t] != 0u) b64s = 0;
    __syncthreads();
    if (t == 0) { g_flags[0] = e64s; g_flags[1] = b64s; }
}

// Transpose + bf16 hi/lo split of all layer weights, packed 2-k-per-word.
__global__ void k_wprep(const float* __restrict__ wrel, const float* __restrict__ wroot) {
    int idx = blockIdx.x * 256 + threadIdx.x;
    const int WORDS = N_LAYERS * 2 * D * (D / 2);   // 114688
    if (idx >= WORDS) return;
    int l = idx >> 14;            // / 16384
    int rem = idx & 16383;
    int mat = rem >> 13;
    int r2 = rem & 8191;
    int n = r2 >> 6;
    int wk = r2 & 63;
    int k = wk * 2;
    const float* W = (mat ? wroot : wrel) + (long long)l * D * D;
    float f0 = W[k * D + n];
    float f1 = W[(k + 1) * D + n];
    uint32_t hw, lw;
    split2(f0, f1, hw, lw);
    int base = ((l * 2 + mat) * 2) * 8192 + n * 64 + wk;
    g_wsp[base] = hw;
    g_wsp[base + 8192] = lw;
}

// ---------------- CSR build ----------------
__global__ void k_zero_counts() {
    int i = blockIdx.x * blockDim.x + threadIdx.x;
    if (i < N_NODES) g_counts[i] = 0;
}
__global__ void k_hist(const void* ei) {
    int e = blockIdx.x * blockDim.x + threadIdx.x;
    if (e >= N_EDGES) return;
    int dst = ld_idx(ei, (long long)N_EDGES + e, g_flags[0]);
    atomicAdd(&g_counts[dst], 1);
}
__global__ void k_scan1() {
    __shared__ int s[1024];
    int blk = blockIdx.x, t = threadIdx.x;
    int idx = blk * 1024 + t;
    int v = (idx < N_NODES) ? g_counts[idx] : 0;
    s[t] = v;
    __syncthreads();
    for (int off = 1; off < 1024; off <<= 1) {
        int add = (t >= off) ? s[t - off] : 0;
        __syncthreads();
        s[t] += add;
        __syncthreads();
    }
    if (idx < N_NODES) g_rowptr[idx] = s[t];
    if (t == 1023) g_blocksums[blk] = s[t];
}
__global__ void k_scan2(int nblocks) {
    if (blockIdx.x == 0 && threadIdx.x == 0) {
        int acc = 0;
        for (int b = 0; b < nblocks; b++) { int v = g_blocksums[b]; g_blocksums[b] = acc; acc += v; }
        g_rowptr[N_NODES] = N_EDGES;
    }
}
__global__ void k_scan3() {
    int i = blockIdx.x * blockDim.x + threadIdx.x;
    if (i < N_NODES) {
        int ex = g_rowptr[i] - g_counts[i] + g_blocksums[i >> 10];
        g_rowptr[i] = ex;
        g_wptr[i] = ex;
    }
}
__global__ void k_scatter(const void* ei) {
    int e = blockIdx.x * blockDim.x + threadIdx.x;
    if (e >= N_EDGES) return;
    int is64 = g_flags[0];
    int src = ld_idx(ei, e, is64);
    int dst = ld_idx(ei, (long long)N_EDGES + e, is64);
    int pos = atomicAdd(&g_wptr[dst], 1);
    g_esrc[pos] = src;
}

// ---------------- aggregation: one warp per node ----------------
__global__ void k_agg(const float* __restrict__ h, float* __restrict__ agg) {
    int warp = (blockIdx.x * blockDim.x + threadIdx.x) >> 5;
    int lane = threadIdx.x & 31;
    if (warp >= N_NODES) return;
    int s = g_rowptr[warp];
    int e = g_rowptr[warp + 1];
    float4 acc = make_float4(0.f, 0.f, 0.f, 0.f);
    for (int i = s; i < e; i++) {
        int src = g_esrc[i];
        float4 v = *(const float4*)&h[(long long)src * D + lane * 4];
        acc.x += v.x; acc.y += v.y; acc.z += v.z; acc.w += v.w;
    }
    *(float4*)&agg[(long long)warp * D + lane * 4] = acc;
}

// ---------------- 3xBF16 mma.sync GraphConv GEMM (m16n8k16) ----------------
// C[m,:] = relu( A1[m,:] @ W1 + A2[m,:] @ W2 + bias )
// CTA tile 128x128; K = 2x128 in 8 chunks of 32.
// SMEM tiles: [128 rows][32 k] bf16, row stride 80B (ldmatrix conflict-free).
#define RSTR 80
#define SM_AH 0
#define SM_AL 10240
#define SM_BH 20480
#define SM_BL 30720
#define GEMM_SMEM 40960

__global__ __launch_bounds__(256, 2)
void k_gemm_bf16(const float* __restrict__ A1, const float* __restrict__ A2,
                 const uint32_t* __restrict__ Wt,   // layer base: 4 tiles of 8192 words
                 const float* __restrict__ bias, float* __restrict__ C) {
    __shared__ __align__(16) char smc[GEMM_SMEM];
    const uint32_t sbase = smem_u32(smc);
    const int tid = threadIdx.x;
    const int w = tid >> 5;
    const int lane = tid & 31;
    const int g = lane >> 2;
    const int tg = lane & 3;
    const int bm = blockIdx.x * 128;
    const int mbase = (w & 3) * 32;
    const int nbase = (w >> 2) * 64;

    float acc[2][8][4];
#pragma unroll
    for (int mt = 0; mt < 2; mt++)
#pragma unroll
        for (int nt = 0; nt < 8; nt++)
#pragma unroll
            for (int q = 0; q < 4; q++) acc[mt][nt][q] = 0.f;

    const int srow = tid >> 3;          // 0..31, +32 per it
    const int sq = tid & 7;             // k-quad (4 k values)

    // prefetch chunk 0's A slice into registers
    float4 pa[4];
#pragma unroll
    for (int it = 0; it < 4; it++) {
        int row = it * 32 + srow;
        pa[it] = (bm + row < N_NODES)
                 ? *(const float4*)&A1[(long long)(bm + row) * 128 + sq * 4]
                 : make_float4(0.f, 0.f, 0.f, 0.f);
    }

    // ldmatrix lane addressing
    const int aRow16 = lane & 15;
    const uint32_t aSel = (uint32_t)(lane >> 4) * 16u;   // +16B for k8..15
    const int bRow = lane & 7;
    const uint32_t bK = (uint32_t)((lane >> 3) & 1) * 16u;

    for (int c = 0; c < 8; c++) {
        const int k0w = (c & 3) * 16;    // word offset into 64-word k rows
        const uint32_t* Whi = Wt + ((c >> 2) * 2) * 8192;
        const uint32_t* Wlo = Whi + 8192;

        // ---- stage A (split hi/lo) + B (pre-split) ----
#pragma unroll
        for (int it = 0; it < 4; it++) {
            int row = it * 32 + srow;
            uint32_t off = (uint32_t)(row * RSTR + sq * 8);
            float4 v = pa[it];
            uint32_t h01, l01, h23, l23;
            split2(v.x, v.y, h01, l01);
            split2(v.z, v.w, h23, l23);
            *(uint2*)(smc + SM_AH + off) = make_uint2(h01, h23);
            *(uint2*)(smc + SM_AL + off) = make_uint2(l01, l23);
            *(uint2*)(smc + SM_BH + off) = *(const uint2*)&Whi[row * 64 + k0w + sq * 2];
            *(uint2*)(smc + SM_BL + off) = *(const uint2*)&Wlo[row * 64 + k0w + sq * 2];
        }
        __syncthreads();

        // ---- prefetch next chunk's A ----
        if (c < 7) {
            const float* An = ((c + 1) < 4) ? A1 : A2;
            const int k0n = ((c + 1) & 3) * 32;
#pragma unroll
            for (int it = 0; it < 4; it++) {
                int row = it * 32 + srow;
                pa[it] = (bm + row < N_NODES)
                         ? *(const float4*)&An[(long long)(bm + row) * 128 + k0n + sq * 4]
                         : make_float4(0.f, 0.f, 0.f, 0.f);
            }
        }

        // ---- compute: 2 k16-steps ----
#pragma unroll
        for (int ks = 0; ks < 2; ks++) {
            uint32_t ah[2][4], al[2][4];
#pragma unroll
            for (int mt = 0; mt < 2; mt++) {
                uint32_t base = sbase + (uint32_t)((mbase + mt * 16 + aRow16) * RSTR)
                              + (uint32_t)ks * 32u + aSel;
                ldsm_x4(ah[mt], base + SM_AH);
                ldsm_x4(al[mt], base + SM_AL);
            }
#pragma unroll
            for (int nt = 0; nt < 8; nt++) {
                uint32_t bb = sbase + (uint32_t)((nbase + nt * 8 + bRow) * RSTR)
                            + (uint32_t)ks * 32u + bK;
                uint32_t bh[2], bl[2];
                ldsm_x2(bh, bb + SM_BH);
                ldsm_x2(bl, bb + SM_BL);
#pragma unroll
                for (int mt = 0; mt < 2; mt++) {
                    mma_bf16(acc[mt][nt], ah[mt], bh[0], bh[1]);
                    mma_bf16(acc[mt][nt], ah[mt], bl[0], bl[1]);
                    mma_bf16(acc[mt][nt], al[mt], bh[0], bh[1]);
                }
            }
        }
        __syncthreads();
    }

    // ---- epilogue: bias + relu, float2 stores ----
#pragma unroll
    for (int mt = 0; mt < 2; mt++) {
        int row0 = bm + mbase + mt * 16 + g;
        int row1 = row0 + 8;
#pragma unroll
        for (int nt = 0; nt < 8; nt++) {
            int col = nbase + nt * 8 + 2 * tg;
            float b0 = bias[col];
            float b1 = bias[col + 1];
            if (row0 < N_NODES) {
                float2 o;
                o.x = fmaxf(acc[mt][nt][0] + b0, 0.f);
                o.y = fmaxf(acc[mt][nt][1] + b1, 0.f);
                *(float2*)&C[(long long)row0 * 128 + col] = o;
            }
            if (row1 < N_NODES) {
                float2 o;
                o.x = fmaxf(acc[mt][nt][2] + b0, 0.f);
                o.y = fmaxf(acc[mt][nt][3] + b1, 0.f);
                *(float2*)&C[(long long)row1 * 128 + col] = o;
            }
        }
    }
}

// ---------------- pooling / SNN / fusion ----------------
__global__ void k_zero_pool() {
    int i = blockIdx.x * blockDim.x + threadIdx.x;
    if (i < N_GRAPHS * D) g_pool[i] = 0.f;
    if (i < N_GRAPHS) g_cnt[i] = 0.f;
}

#define PCHUNK 256
__global__ void k_pool(const float* __restrict__ h, const void* bt) {
    int blk = blockIdx.x;
    int f = threadIdx.x;
    int start = blk * PCHUNK;
    if (start >= N_NODES) return;
    int end = start + PCHUNK;
    if (end > N_NODES) end = N_NODES;
    int is64 = g_flags[1];
    int cur = ld_idx(bt, start, is64);
    float s = 0.f, c = 0.f;
    for (int n = start; n < end; n++) {
        int g = ld_idx(bt, n, is64);
        if (g != cur) {
            atomicAdd(&g_pool[cur * D + f], s);
            if (f == 0) atomicAdd(&g_cnt[cur], c);
            s = 0.f; c = 0.f; cur = g;
        }
        s += h[(long long)n * D + f];
        c += 1.f;
    }
    atomicAdd(&g_pool[cur * D + f], s);
    if (f == 0) atomicAdd(&g_cnt[cur], c);
}

__global__ void k_snn1(const float* __restrict__ x, const float* __restrict__ w1,
                       const float* __restrict__ b1) {
    int g = blockIdx.x;
    int t = threadIdx.x;   // 256
    __shared__ float xs[SNN_IN];
    for (int i = t; i < SNN_IN; i += 256) xs[i] = x[g * SNN_IN + i];
    __syncthreads();
    for (int j = t; j < SNN_HID; j += 256) {
        float a = b1[j];
        for (int k = 0; k < SNN_IN; k++)
            a += xs[k] * w1[k * SNN_HID + j];
        g_snnh[g * SNN_HID + j] = fmaxf(a, 0.f);
    }
}

__global__ void k_final(const float* __restrict__ lin_w, const float* __restrict__ lin_b,
                        const float* __restrict__ w2, const float* __restrict__ b2,
                        const float* __restrict__ fuse_w, const float* __restrict__ fuse_b,
                        float* __restrict__ out) {
    int g = blockIdx.x;
    int t = threadIdx.x;   // 128
    __shared__ float mean[D];
    __shared__ float red[128];
    __shared__ float snl[N_CLASSES], gnl[N_CLASSES];
    float cnt = fmaxf(g_cnt[g], 1.f);
    mean[t] = g_pool[g * D + t] / cnt;
    __syncthreads();
    for (int c = 0; c < N_CLASSES; c++) {
        red[t] = mean[t] * lin_w[t * N_CLASSES + c];
        for (int off = 64; off > 0; off >>= 1) {
            __syncthreads();
            if (t < off) red[t] += red[t + off];
        }
        __syncthreads();
        if (t == 0) gnl[c] = red[0] + lin_b[c];
        __syncthreads();
    }
    for (int c = 0; c < N_CLASSES; c++) {
        float p = 0.f;
        for (int k = t; k < SNN_HID; k += 128)
            p += g_snnh[g * SNN_HID + k] * w2[k * N_CLASSES + c];
        red[t] = p;
        for (int off = 64; off > 0; off >>= 1) {
            __syncthreads();
            if (t < off) red[t] += red[t + off];
        }
        __syncthreads();
        if (t == 0) snl[c] = SNN_BETA * (red[0] + b2[c]);
        __syncthreads();
    }
    if (t < N_CLASSES) {
        float o = fuse_b[t];
        for (int j = 0; j < N_CLASSES; j++) {
            o += snl[j] * fuse_w[j * N_CLASSES + t];
            o += gnl[j] * fuse_w[(N_CLASSES + j) * N_CLASSES + t];
        }
        out[g * N_CLASSES + t] = o;
    }
}

// ---------------- launch ----------------
extern "C" void kernel_launch(void* const* d_in, const int* in_sizes, int n_in,
                              void* d_out, int out_size) {
    const float* snn_x  = (const float*)d_in[0];
    const float* x      = (const float*)d_in[1];
    const void*  ei     = d_in[2];
    const void*  bt     = d_in[3];
    const float* snn_w1 = (const float*)d_in[4];
    const float* snn_b1 = (const float*)d_in[5];
    const float* snn_w2 = (const float*)d_in[6];
    const float* snn_b2 = (const float*)d_in[7];
    const float* wrel   = (const float*)d_in[8];
    const float* wroot  = (const float*)d_in[9];
    const float* brel   = (const float*)d_in[10];
    const float* lin_w  = (const float*)d_in[11];
    const float* lin_b  = (const float*)d_in[12];
    const float* fuse_w = (const float*)d_in[13];
    const float* fuse_b = (const float*)d_in[14];
    float* out = (float*)d_out;

    void* p;
    cudaGetSymbolAddress(&p, g_h0);   float* h0  = (float*)p;
    cudaGetSymbolAddress(&p, g_h1);   float* h1  = (float*)p;
    cudaGetSymbolAddress(&p, g_agg);  float* agp = (float*)p;
    cudaGetSymbolAddress(&p, g_wsp);  uint32_t* wsp = (uint32_t*)p;

    k_detect<<<1, 256>>>((const unsigned int*)ei, (const unsigned int*)bt);
    k_wprep<<<(N_LAYERS * 2 * D * (D / 2) + 255) / 256, 256>>>(wrel, wroot);

    // CSR build (by dst)
    k_zero_counts<<<(N_NODES + 255) / 256, 256>>>();
    k_hist<<<(N_EDGES + 255) / 256, 256>>>(ei);
    const int nsb = (N_NODES + 1023) / 1024;   // 98
    k_scan1<<<nsb, 1024>>>();
    k_scan2<<<1, 1>>>(nsb);
    k_scan3<<<(N_NODES + 255) / 256, 256>>>();
    k_scatter<<<(N_EDGES + 255) / 256, 256>>>(ei);

    // 7 GraphConv layers; layer 0 consumes x directly
    const float* hin = x;
    float* hout = h1;
    const int aggBlocks = (N_NODES * 32 + 255) / 256;
    const int gemmBlocks = (N_NODES + 127) / 128;   // 782
    for (int l = 0; l < N_LAYERS; l++) {
        k_agg<<<aggBlocks, 256>>>(hin, agp);
        k_gemm_bf16<<<gemmBlocks, 256>>>(agp, hin,
                                         wsp + (long long)l * 4 * 8192,
                                         brel + (long long)l * D, hout);
        hin = hout;
        hout = (hout == h1) ? h0 : h1;
    }

    // global mean pool
    k_zero_pool<<<(N_GRAPHS * D + 255) / 256, 256>>>();
    k_pool<<<(N_NODES + PCHUNK - 1) / PCHUNK, 128>>>(hin, bt);

    // SNN + fusion
    k_snn1<<<N_GRAPHS, 256>>>(snn_x, snn_w1, snn_b1);
    k_final<<<N_GRAPHS, 128>>>(lin_w, lin_b, snn_w2, snn_b2, fuse_w, fuse_b, out);
}